// round 3
// baseline (speedup 1.0000x reference)
#include <cuda_runtime.h>
#include <cuda_bf16.h>

#define N_NODES 100000
#define N_EDGES 3200000
#define D 128            // D_IN == D_OUT == 128
#define D4 32            // D / 4 (float4 per row)
#define EPW 256          // edges per warp in SpMM (3.2M / 256 = 12500 warps exactly)
#define GRP 8            // gather batch (MLP) in SpMM

// Scratch for y = x @ W (51.2 MB). __device__ global: allowed scratch, no allocation.
__device__ float g_y[(size_t)N_NODES * D];

// ---------------------------------------------------------------------------
// Kernel 1: y = x @ W   (fp32 SIMT GEMM)
// Block = 256 threads (tx in [0,32) -> 4-col group, ty in [0,8) -> row lane).
// Tile = 64 rows x 128 cols. Each thread: acc[8] float4 (8 rows x 4 cols).
// X tile staged in smem (32 KB); W read through L1 (64 KB, hot after 1st tile).
// ---------------------------------------------------------------------------
__device__ __forceinline__ void fma4(float4& a, float s, const float4& b) {
    a.x = fmaf(s, b.x, a.x);
    a.y = fmaf(s, b.y, a.y);
    a.z = fmaf(s, b.z, a.z);
    a.w = fmaf(s, b.w, a.w);
}

__global__ __launch_bounds__(256) void gemm_xw_kernel(
    const float* __restrict__ x, const float* __restrict__ W)
{
    __shared__ float4 Xs[64][D4];  // 64 rows x 128 cols = 32 KB

    const int row0 = blockIdx.x * 64;
    const int tid  = threadIdx.x;

    // Cooperative load of the 64-row X tile (coalesced float4).
    const float4* x4 = reinterpret_cast<const float4*>(x);
    #pragma unroll
    for (int i = tid; i < 64 * D4; i += 256) {
        int r = i >> 5;         // i / 32
        int c = i & 31;
        int gr = row0 + r;
        float4 v = make_float4(0.f, 0.f, 0.f, 0.f);
        if (gr < N_NODES) v = x4[(size_t)gr * D4 + c];
        Xs[r][c] = v;
    }
    __syncthreads();

    const int tx = tid & 31;   // column group: cols [4*tx, 4*tx+4)
    const int ty = tid >> 5;   // row lane: rows ty, ty+8, ..., ty+56

    float4 acc[8];
    #pragma unroll
    for (int i = 0; i < 8; i++) acc[i] = make_float4(0.f, 0.f, 0.f, 0.f);

    const float4* W4 = reinterpret_cast<const float4*>(W);

    #pragma unroll 4
    for (int k4 = 0; k4 < D4; k4++) {
        // W rows 4*k4 .. 4*k4+3, columns [4*tx, 4*tx+4)
        float4 w0 = __ldg(&W4[(size_t)(4 * k4 + 0) * D4 + tx]);
        float4 w1 = __ldg(&W4[(size_t)(4 * k4 + 1) * D4 + tx]);
        float4 w2 = __ldg(&W4[(size_t)(4 * k4 + 2) * D4 + tx]);
        float4 w3 = __ldg(&W4[(size_t)(4 * k4 + 3) * D4 + tx]);
        #pragma unroll
        for (int i = 0; i < 8; i++) {
            float4 xv = Xs[ty + 8 * i][k4];   // broadcast across the warp
            fma4(acc[i], xv.x, w0);
            fma4(acc[i], xv.y, w1);
            fma4(acc[i], xv.z, w2);
            fma4(acc[i], xv.w, w3);
        }
    }

    float4* y4 = reinterpret_cast<float4*>(g_y);
    #pragma unroll
    for (int i = 0; i < 8; i++) {
        int row = row0 + ty + 8 * i;
        if (row < N_NODES) y4[(size_t)row * D4 + tx] = acc[i];
    }
}

// ---------------------------------------------------------------------------
// Kernel 2: out[r] += val_e * y[col_e]  (edges sorted by row)
// One warp handles EPW consecutive edges; 32 lanes x float4 cover D=128.
// Edges processed in groups of GRP=8: batch-load indices, issue all 8 gather
// LDG.128s (guaranteed MLP=8, independent of atomics below), then
// flush/accumulate. Register-accumulate per row run, atomicAdd flush only
// on row change (~1 per 32 edges, rows are sorted).
// ---------------------------------------------------------------------------
__global__ __launch_bounds__(128) void spmm_kernel(
    const int*   __restrict__ erow,
    const int*   __restrict__ ecol,
    const float* __restrict__ eval,
    float*       __restrict__ out)
{
    const int warp = (blockIdx.x * blockDim.x + threadIdx.x) >> 5;
    const int lane = threadIdx.x & 31;
    const long e0  = (long)warp * EPW;   // E divides evenly: no tail guard needed

    const float4* y4 = reinterpret_cast<const float4*>(g_y);

    float4 acc = make_float4(0.f, 0.f, 0.f, 0.f);
    int cur = __ldg(&erow[e0]);

    for (int j0 = 0; j0 < EPW; j0 += GRP) {
        int   r[GRP];
        int   c[GRP];
        float v[GRP];
        float4 g[GRP];

        // Batch the scalar edge loads (uniform across warp -> L1 broadcast).
        #pragma unroll
        for (int j = 0; j < GRP; j++) {
            const long e = e0 + j0 + j;
            r[j] = __ldg(&erow[e]);
            c[j] = __ldg(&ecol[e]);
            v[j] = __ldg(&eval[e]);
        }
        // Issue all GRP gathers back-to-back: MLP = GRP.
        #pragma unroll
        for (int j = 0; j < GRP; j++) {
            g[j] = y4[(size_t)c[j] * D4 + lane];
        }
        // Flush on row change (uniform, rare), then accumulate.
        #pragma unroll
        for (int j = 0; j < GRP; j++) {
            if (r[j] != cur) {
                float* o = out + (size_t)cur * D + lane * 4;
                atomicAdd(o + 0, acc.x);
                atomicAdd(o + 1, acc.y);
                atomicAdd(o + 2, acc.z);
                atomicAdd(o + 3, acc.w);
                acc = make_float4(0.f, 0.f, 0.f, 0.f);
                cur = r[j];
            }
            acc.x = fmaf(v[j], g[j].x, acc.x);
            acc.y = fmaf(v[j], g[j].y, acc.y);
            acc.z = fmaf(v[j], g[j].z, acc.z);
            acc.w = fmaf(v[j], g[j].w, acc.w);
        }
    }
    // Final flush.
    float* o = out + (size_t)cur * D + lane * 4;
    atomicAdd(o + 0, acc.x);
    atomicAdd(o + 1, acc.y);
    atomicAdd(o + 2, acc.z);
    atomicAdd(o + 3, acc.w);
}

// ---------------------------------------------------------------------------
// Launch. Inputs (metadata order): x, edge_row, edge_col, edge_val, W.
// Output: float32 [N_NODES, D_OUT].
// ---------------------------------------------------------------------------
extern "C" void kernel_launch(void* const* d_in, const int* in_sizes, int n_in,
                              void* d_out, int out_size)
{
    const float* x    = (const float*)d_in[0];
    const int*   erow = (const int*)  d_in[1];
    const int*   ecol = (const int*)  d_in[2];
    const float* eval = (const float*)d_in[3];
    const float* W    = (const float*)d_in[4];
    float*       out  = (float*)d_out;

    // d_out is poisoned; SpMM accumulates with atomics -> zero it first.
    cudaMemsetAsync(out, 0, (size_t)out_size * sizeof(float), 0);

    // y = x @ W
    const int gemm_blocks = (N_NODES + 63) / 64;   // 1563
    gemm_xw_kernel<<<gemm_blocks, 256>>>(x, W);

    // out = segment_sum(val * y[col], row)
    const int n_warps     = N_EDGES / EPW;          // 12500
    const int spmm_blocks = n_warps / 4;            // 3125 blocks x 128 thr
    spmm_kernel<<<spmm_blocks, 128>>>(erow, ecol, eval, out);
}

// round 4
// speedup vs baseline: 1.0682x; 1.0682x over previous
#include <cuda_runtime.h>
#include <cuda_bf16.h>

#define N_NODES 100000
#define N_EDGES 3200000
#define D 128            // D_IN == D_OUT == 128
#define D4 32            // D / 4 (float4 per row)
#define EPW 256          // edges per warp in SpMM (3.2M / 256 = 12500 warps exactly)
#define GRP 8            // gather batch (MLP) in SpMM

// Scratch for y = x @ W (51.2 MB). __device__ global: allowed scratch, no allocation.
__device__ float g_y[(size_t)N_NODES * D];

// ---------------------------------------------------------------------------
// Kernel 1: y = x @ W   (fp32 SIMT GEMM)
// Block = 256 threads (tx in [0,32) -> 4-col group, ty in [0,8) -> row lane).
// Tile = 64 rows x 128 cols. Each thread: acc[8] float4 (8 rows x 4 cols).
// X tile staged in smem (32 KB); W read through L1 (64 KB, hot after 1st tile).
// ---------------------------------------------------------------------------
__device__ __forceinline__ void fma4(float4& a, float s, const float4& b) {
    a.x = fmaf(s, b.x, a.x);
    a.y = fmaf(s, b.y, a.y);
    a.z = fmaf(s, b.z, a.z);
    a.w = fmaf(s, b.w, a.w);
}

__global__ __launch_bounds__(256) void gemm_xw_kernel(
    const float* __restrict__ x, const float* __restrict__ W)
{
    __shared__ float4 Xs[64][D4];  // 64 rows x 128 cols = 32 KB

    const int row0 = blockIdx.x * 64;
    const int tid  = threadIdx.x;

    // Cooperative load of the 64-row X tile (coalesced float4).
    const float4* x4 = reinterpret_cast<const float4*>(x);
    #pragma unroll
    for (int i = tid; i < 64 * D4; i += 256) {
        int r = i >> 5;         // i / 32
        int c = i & 31;
        int gr = row0 + r;
        float4 v = make_float4(0.f, 0.f, 0.f, 0.f);
        if (gr < N_NODES) v = x4[(size_t)gr * D4 + c];
        Xs[r][c] = v;
    }
    __syncthreads();

    const int tx = tid & 31;   // column group: cols [4*tx, 4*tx+4)
    const int ty = tid >> 5;   // row lane: rows ty, ty+8, ..., ty+56

    float4 acc[8];
    #pragma unroll
    for (int i = 0; i < 8; i++) acc[i] = make_float4(0.f, 0.f, 0.f, 0.f);

    const float4* W4 = reinterpret_cast<const float4*>(W);

    #pragma unroll 4
    for (int k4 = 0; k4 < D4; k4++) {
        // W rows 4*k4 .. 4*k4+3, columns [4*tx, 4*tx+4)
        float4 w0 = __ldg(&W4[(size_t)(4 * k4 + 0) * D4 + tx]);
        float4 w1 = __ldg(&W4[(size_t)(4 * k4 + 1) * D4 + tx]);
        float4 w2 = __ldg(&W4[(size_t)(4 * k4 + 2) * D4 + tx]);
        float4 w3 = __ldg(&W4[(size_t)(4 * k4 + 3) * D4 + tx]);
        #pragma unroll
        for (int i = 0; i < 8; i++) {
            float4 xv = Xs[ty + 8 * i][k4];   // broadcast across the warp
            fma4(acc[i], xv.x, w0);
            fma4(acc[i], xv.y, w1);
            fma4(acc[i], xv.z, w2);
            fma4(acc[i], xv.w, w3);
        }
    }

    float4* y4 = reinterpret_cast<float4*>(g_y);
    #pragma unroll
    for (int i = 0; i < 8; i++) {
        int row = row0 + ty + 8 * i;
        if (row < N_NODES) y4[(size_t)row * D4 + tx] = acc[i];
    }
}

// ---------------------------------------------------------------------------
// Kernel 2: out[r] += val_e * y[col_e]  (edges sorted by row)
// One warp handles EPW consecutive edges; 32 lanes x float4 cover D=128.
// Edge metadata is read with VECTOR loads (int4/float4: 6 wide LDGs per
// 8-edge group instead of 24 scalar LDGs) -> 2.3x fewer LDG issue slots,
// which R3 ncu showed to be the bottleneck (L1=72.9%, LSU issue bound).
// Gathers issued 8 back-to-back (MLP=8). Register-accumulate per sorted-row
// run; atomicAdd flush only on row change (~1 per 32 edges).
// ---------------------------------------------------------------------------
__global__ __launch_bounds__(128) void spmm_kernel(
    const int*   __restrict__ erow,
    const int*   __restrict__ ecol,
    const float* __restrict__ eval,
    float*       __restrict__ out)
{
    const int warp = (blockIdx.x * blockDim.x + threadIdx.x) >> 5;
    const int lane = threadIdx.x & 31;
    const long e0  = (long)warp * EPW;   // multiple of 256 -> int4-aligned

    // Vector views of this warp's edge slice (uniform across warp -> L1 bcast).
    const int4*   r4 = reinterpret_cast<const int4*>(erow + e0);
    const int4*   c4 = reinterpret_cast<const int4*>(ecol + e0);
    const float4* v4 = reinterpret_cast<const float4*>(eval + e0);

    const float4* y4 = reinterpret_cast<const float4*>(g_y);

    float4 acc = make_float4(0.f, 0.f, 0.f, 0.f);
    int cur = __ldg(&erow[e0]);

    for (int q = 0; q < EPW / GRP; q++) {     // 32 groups of 8 edges
        // 6 wide metadata loads covering 8 edges.
        int4   ra = __ldg(&r4[2 * q]);
        int4   rb = __ldg(&r4[2 * q + 1]);
        int4   ca = __ldg(&c4[2 * q]);
        int4   cb = __ldg(&c4[2 * q + 1]);
        float4 va = __ldg(&v4[2 * q]);
        float4 vb = __ldg(&v4[2 * q + 1]);

        int   r[GRP] = {ra.x, ra.y, ra.z, ra.w, rb.x, rb.y, rb.z, rb.w};
        int   c[GRP] = {ca.x, ca.y, ca.z, ca.w, cb.x, cb.y, cb.z, cb.w};
        float v[GRP] = {va.x, va.y, va.z, va.w, vb.x, vb.y, vb.z, vb.w};

        // Issue all GRP gathers back-to-back: MLP = GRP.
        float4 g[GRP];
        #pragma unroll
        for (int j = 0; j < GRP; j++) {
            g[j] = y4[(size_t)c[j] * D4 + lane];
        }
        // Flush on row change (uniform across warp, rare), then accumulate.
        #pragma unroll
        for (int j = 0; j < GRP; j++) {
            if (r[j] != cur) {
                float* o = out + (size_t)cur * D + lane * 4;
                atomicAdd(o + 0, acc.x);
                atomicAdd(o + 1, acc.y);
                atomicAdd(o + 2, acc.z);
                atomicAdd(o + 3, acc.w);
                acc = make_float4(0.f, 0.f, 0.f, 0.f);
                cur = r[j];
            }
            acc.x = fmaf(v[j], g[j].x, acc.x);
            acc.y = fmaf(v[j], g[j].y, acc.y);
            acc.z = fmaf(v[j], g[j].z, acc.z);
            acc.w = fmaf(v[j], g[j].w, acc.w);
        }
    }
    // Final flush.
    float* o = out + (size_t)cur * D + lane * 4;
    atomicAdd(o + 0, acc.x);
    atomicAdd(o + 1, acc.y);
    atomicAdd(o + 2, acc.z);
    atomicAdd(o + 3, acc.w);
}

// ---------------------------------------------------------------------------
// Launch. Inputs (metadata order): x, edge_row, edge_col, edge_val, W.
// Output: float32 [N_NODES, D_OUT].
// ---------------------------------------------------------------------------
extern "C" void kernel_launch(void* const* d_in, const int* in_sizes, int n_in,
                              void* d_out, int out_size)
{
    const float* x    = (const float*)d_in[0];
    const int*   erow = (const int*)  d_in[1];
    const int*   ecol = (const int*)  d_in[2];
    const float* eval = (const float*)d_in[3];
    const float* W    = (const float*)d_in[4];
    float*       out  = (float*)d_out;

    // d_out is poisoned; SpMM accumulates with atomics -> zero it first.
    cudaMemsetAsync(out, 0, (size_t)out_size * sizeof(float), 0);

    // y = x @ W
    const int gemm_blocks = (N_NODES + 63) / 64;   // 1563
    gemm_xw_kernel<<<gemm_blocks, 256>>>(x, W);

    // out = segment_sum(val * y[col], row)
    const int n_warps     = N_EDGES / EPW;          // 12500
    const int spmm_blocks = n_warps / 4;            // 3125 blocks x 128 thr
    spmm_kernel<<<spmm_blocks, 128>>>(erow, ecol, eval, out);
}

// round 14
// speedup vs baseline: 1.1437x; 1.0707x over previous
#include <cuda_runtime.h>
#include <cuda_bf16.h>

#define N_NODES 100000
#define N_EDGES 3200000
#define D 128            // D_IN == D_OUT == 128
#define D4 32            // D / 4 (float4 per row)
#define EPW 256          // edges per warp in SpMM (3.2M / 256 = 12500 warps exactly)
#define GRP 8            // gather batch (MLP) in SpMM

typedef unsigned long long u64;

// Scratch for y = x @ W (51.2 MB). __device__ global: allowed scratch, no allocation.
__device__ float g_y[(size_t)N_NODES * D];

// ---- packed f32x2 helpers (Blackwell: 2 exact fp32 FMAs per instruction) ----
__device__ __forceinline__ u64 pack2(float lo, float hi) {
    u64 r;
    asm("mov.b64 %0, {%1, %2};" : "=l"(r) : "f"(lo), "f"(hi));
    return r;
}
__device__ __forceinline__ void unpack2(u64 p, float& lo, float& hi) {
    asm("mov.b64 {%0, %1}, %2;" : "=f"(lo), "=f"(hi) : "l"(p));
}
__device__ __forceinline__ void ffma2(u64& d, u64 a, u64 b) {
    asm("fma.rn.f32x2 %0, %1, %2, %0;" : "+l"(d) : "l"(a), "l"(b));
}

// ---------------------------------------------------------------------------
// Kernel 1: y = x @ W   (fp32 GEMM using packed fma.rn.f32x2 -> half the
// fma-pipe instructions of scalar FFMA; results bit-identical to fp32).
// Also zeroes its slice of `out` (fused memset).
// Block = 256 threads. Tile = 64 rows x 128 cols; acc = 8 rows x 4 cols/thread
// held as two f32x2 lanes (accL = cols {x,y}, accH = cols {z,w}).
// ---------------------------------------------------------------------------
__global__ __launch_bounds__(256) void gemm_xw_kernel(
    const float* __restrict__ x, const float* __restrict__ W,
    float* __restrict__ out)
{
    __shared__ float4 Xs[64][D4];  // 64 rows x 128 cols = 32 KB

    const int row0 = blockIdx.x * 64;
    const int tid  = threadIdx.x;

    // Fused zeroing of this block's 64 output rows (overlaps with GEMM work).
    {
        float4 z = make_float4(0.f, 0.f, 0.f, 0.f);
        float4* o4 = reinterpret_cast<float4*>(out);
        #pragma unroll
        for (int i = tid; i < 64 * D4; i += 256) {
            int r = row0 + (i >> 5);
            if (r < N_NODES) o4[(size_t)r * D4 + (i & 31)] = z;
        }
    }

    // Cooperative load of the 64-row X tile (coalesced float4).
    const float4* x4 = reinterpret_cast<const float4*>(x);
    #pragma unroll
    for (int i = tid; i < 64 * D4; i += 256) {
        int r = i >> 5;
        int c = i & 31;
        int gr = row0 + r;
        float4 v = make_float4(0.f, 0.f, 0.f, 0.f);
        if (gr < N_NODES) v = x4[(size_t)gr * D4 + c];
        Xs[r][c] = v;
    }
    __syncthreads();

    const int tx = tid & 31;   // column group: cols [4*tx, 4*tx+4)
    const int ty = tid >> 5;   // row lane: rows ty, ty+8, ..., ty+56

    u64 accL[8], accH[8];
    #pragma unroll
    for (int i = 0; i < 8; i++) { accL[i] = 0ull; accH[i] = 0ull; }

    const float4* W4 = reinterpret_cast<const float4*>(W);

    #pragma unroll 4
    for (int k4 = 0; k4 < D4; k4++) {
        // W rows 4*k4 .. 4*k4+3, columns [4*tx, 4*tx+4), packed into f32x2.
        float4 w0 = __ldg(&W4[(size_t)(4 * k4 + 0) * D4 + tx]);
        float4 w1 = __ldg(&W4[(size_t)(4 * k4 + 1) * D4 + tx]);
        float4 w2 = __ldg(&W4[(size_t)(4 * k4 + 2) * D4 + tx]);
        float4 w3 = __ldg(&W4[(size_t)(4 * k4 + 3) * D4 + tx]);
        u64 w0L = pack2(w0.x, w0.y), w0H = pack2(w0.z, w0.w);
        u64 w1L = pack2(w1.x, w1.y), w1H = pack2(w1.z, w1.w);
        u64 w2L = pack2(w2.x, w2.y), w2H = pack2(w2.z, w2.w);
        u64 w3L = pack2(w3.x, w3.y), w3H = pack2(w3.z, w3.w);

        #pragma unroll
        for (int i = 0; i < 8; i++) {
            float4 xv = Xs[ty + 8 * i][k4];   // broadcast across the warp
            u64 sx = pack2(xv.x, xv.x);
            u64 sy = pack2(xv.y, xv.y);
            u64 sz = pack2(xv.z, xv.z);
            u64 sw = pack2(xv.w, xv.w);
            ffma2(accL[i], sx, w0L); ffma2(accH[i], sx, w0H);
            ffma2(accL[i], sy, w1L); ffma2(accH[i], sy, w1H);
            ffma2(accL[i], sz, w2L); ffma2(accH[i], sz, w2H);
            ffma2(accL[i], sw, w3L); ffma2(accH[i], sw, w3H);
        }
    }

    float4* y4 = reinterpret_cast<float4*>(g_y);
    #pragma unroll
    for (int i = 0; i < 8; i++) {
        int row = row0 + ty + 8 * i;
        if (row < N_NODES) {
            float4 r;
            unpack2(accL[i], r.x, r.y);
            unpack2(accH[i], r.z, r.w);
            y4[(size_t)row * D4 + tx] = r;
        }
    }
}

// ---------------------------------------------------------------------------
// Kernel 2: out[r] += val_e * y[col_e]  (edges sorted by row)
// One warp handles EPW consecutive edges; 32 lanes x float4 cover D=128.
// Metadata via vector loads (R4 win). Gathers issued 8 back-to-back (MLP=8).
// Flushes use ONE red.global.add.v4.f32 per lane (issue ~= STG.128)
// instead of 4 scalar atomicAdds (R4 ncu: atomics were ~half the LSU time).
// ---------------------------------------------------------------------------
__device__ __forceinline__ void red_add_v4(float* addr, const float4& a) {
    asm volatile("red.global.add.v4.f32 [%0], {%1, %2, %3, %4};"
                 :: "l"(addr), "f"(a.x), "f"(a.y), "f"(a.z), "f"(a.w)
                 : "memory");
}

__global__ __launch_bounds__(128) void spmm_kernel(
    const int*   __restrict__ erow,
    const int*   __restrict__ ecol,
    const float* __restrict__ eval,
    float*       __restrict__ out)
{
    const int warp = (blockIdx.x * blockDim.x + threadIdx.x) >> 5;
    const int lane = threadIdx.x & 31;
    const long e0  = (long)warp * EPW;   // multiple of 256 -> int4-aligned

    // Vector views of this warp's edge slice (uniform across warp -> L1 bcast).
    const int4*   r4 = reinterpret_cast<const int4*>(erow + e0);
    const int4*   c4 = reinterpret_cast<const int4*>(ecol + e0);
    const float4* v4 = reinterpret_cast<const float4*>(eval + e0);

    const float4* y4 = reinterpret_cast<const float4*>(g_y);

    float4 acc = make_float4(0.f, 0.f, 0.f, 0.f);
    int cur = __ldg(&erow[e0]);

    for (int q = 0; q < EPW / GRP; q++) {     // 32 groups of 8 edges
        // 6 wide metadata loads covering 8 edges.
        int4   ra = __ldg(&r4[2 * q]);
        int4   rb = __ldg(&r4[2 * q + 1]);
        int4   ca = __ldg(&c4[2 * q]);
        int4   cb = __ldg(&c4[2 * q + 1]);
        float4 va = __ldg(&v4[2 * q]);
        float4 vb = __ldg(&v4[2 * q + 1]);

        int   r[GRP] = {ra.x, ra.y, ra.z, ra.w, rb.x, rb.y, rb.z, rb.w};
        int   c[GRP] = {ca.x, ca.y, ca.z, ca.w, cb.x, cb.y, cb.z, cb.w};
        float v[GRP] = {va.x, va.y, va.z, va.w, vb.x, vb.y, vb.z, vb.w};

        // Issue all GRP gathers back-to-back: MLP = GRP.
        float4 g[GRP];
        #pragma unroll
        for (int j = 0; j < GRP; j++) {
            g[j] = y4[(size_t)c[j] * D4 + lane];
        }
        // Flush on row change (uniform across warp, rare), then accumulate.
        #pragma unroll
        for (int j = 0; j < GRP; j++) {
            if (r[j] != cur) {
                red_add_v4(out + (size_t)cur * D + lane * 4, acc);
                acc = make_float4(0.f, 0.f, 0.f, 0.f);
                cur = r[j];
            }
            acc.x = fmaf(v[j], g[j].x, acc.x);
            acc.y = fmaf(v[j], g[j].y, acc.y);
            acc.z = fmaf(v[j], g[j].z, acc.z);
            acc.w = fmaf(v[j], g[j].w, acc.w);
        }
    }
    // Final flush.
    red_add_v4(out + (size_t)cur * D + lane * 4, acc);
}

// ---------------------------------------------------------------------------
// Launch. Inputs (metadata order): x, edge_row, edge_col, edge_val, W.
// Output: float32 [N_NODES, D_OUT].
// ---------------------------------------------------------------------------
extern "C" void kernel_launch(void* const* d_in, const int* in_sizes, int n_in,
                              void* d_out, int out_size)
{
    const float* x    = (const float*)d_in[0];
    const int*   erow = (const int*)  d_in[1];
    const int*   ecol = (const int*)  d_in[2];
    const float* eval = (const float*)d_in[3];
    const float* W    = (const float*)d_in[4];
    float*       out  = (float*)d_out;

    // y = x @ W  (also zeroes `out` for the SpMM's reductions)
    const int gemm_blocks = (N_NODES + 63) / 64;   // 1563
    gemm_xw_kernel<<<gemm_blocks, 256>>>(x, W, out);

    // out = segment_sum(val * y[col], row)
    const int n_warps     = N_EDGES / EPW;          // 12500
    const int spmm_blocks = n_warps / 4;            // 3125 blocks x 128 thr
    spmm_kernel<<<spmm_blocks, 128>>>(erow, ecol, eval, out);
}